// round 6
// baseline (speedup 1.0000x reference)
#include <cuda_runtime.h>
#include <cuda_bf16.h>
#include <cstdint>

#define DIM 128
#define NTH 384
#define WARPS 12
#define PI_F 3.14159265358979323846f

// ---- smem byte offsets: 4 weight tiles (32 KB each, swizzled) + biases ----
#define OFF_W1H 0
#define OFF_W1L 32768
#define OFF_W2H 65536
#define OFF_W2L 98304
#define OFF_B1  131072
#define OFF_B2  131584
#define SMEM_TOTAL 132096

// swizzled byte offset in a [128 rows x 128 k] bf16 tile, 256B/row
__device__ __forceinline__ uint32_t swz(int row, int kElem) {
    return (uint32_t)(row * 256) + (((uint32_t)(kElem * 2)) ^ (uint32_t)((row & 7) << 4));
}

__device__ __forceinline__ uint32_t smem_u32(const void* p) {
    uint32_t a;
    asm("{ .reg .u64 t; cvta.to.shared.u64 t, %1; cvt.u32.u64 %0, t; }" : "=r"(a) : "l"(p));
    return a;
}

__device__ __forceinline__ void ldsm4(uint32_t& r0, uint32_t& r1, uint32_t& r2, uint32_t& r3,
                                      uint32_t addr) {
    asm volatile("ldmatrix.sync.aligned.m8n8.x4.shared.b16 {%0,%1,%2,%3}, [%4];"
                 : "=r"(r0), "=r"(r1), "=r"(r2), "=r"(r3) : "r"(addr));
}

__device__ __forceinline__ void mma16816(float* c, const uint32_t* a, uint32_t b0, uint32_t b1) {
    asm volatile(
        "mma.sync.aligned.m16n8k16.row.col.f32.bf16.bf16.f32 "
        "{%0,%1,%2,%3}, {%4,%5,%6,%7}, {%8,%9}, {%0,%1,%2,%3};"
        : "+f"(c[0]), "+f"(c[1]), "+f"(c[2]), "+f"(c[3])
        : "r"(a[0]), "r"(a[1]), "r"(a[2]), "r"(a[3]), "r"(b0), "r"(b1));
}

__device__ __forceinline__ uint32_t pack2(__nv_bfloat16 a, __nv_bfloat16 b) {
    return ((uint32_t)__bfloat16_as_ushort(b) << 16) | (uint32_t)__bfloat16_as_ushort(a);
}

// split (x0,x1) into packed hi and packed lo-residual bf16 pairs (registers)
__device__ __forceinline__ void split2(float x0, float x1, uint32_t& hi, uint32_t& lo) {
    const __nv_bfloat16 h0 = __float2bfloat16(x0), h1 = __float2bfloat16(x1);
    hi = pack2(h0, h1);
    lo = pack2(__float2bfloat16(x0 - __bfloat162float(h0)),
               __float2bfloat16(x1 - __bfloat162float(h1)));
}

// smem split-store used only for weight init
__device__ __forceinline__ void split_store(char* sm, int baseHi, int baseLo,
                                            int row, int k, float x0, float x1) {
    const uint32_t off = swz(row, k);
    uint32_t hi, lo;
    split2(x0, x1, hi, lo);
    *(uint32_t*)(sm + baseHi + off) = hi;
    *(uint32_t*)(sm + baseLo + off) = lo;
}

__device__ __forceinline__ float silu_f(float z) {
    return z / (1.0f + __expf(-z));
}
__device__ __forceinline__ float emb_f(float tv, float p1, float p2, float d) {
    return tv * (__cosf(d * p1) + __sinf(d * p2));
}

__global__ void __launch_bounds__(NTH, 1)
fused_timestep_mlp_rr(const float* __restrict__ t,
                      const float* __restrict__ W1,
                      const float* __restrict__ b1,
                      const float* __restrict__ W2,
                      const float* __restrict__ b2,
                      float* __restrict__ out,
                      int n_chunks) {
    extern __shared__ char sm[];
    const uint32_t sb = smem_u32(sm);
    const int tid = threadIdx.x;
    const int wid = tid >> 5;
    const int lane = tid & 31;

    // ---- weight init: split to hi/lo bf16 swizzled tiles; biases ----
    for (int e = tid * 4; e < DIM * DIM; e += NTH * 4) {
        const int row = e >> 7, k = e & 127;
        const float4 v1 = *(const float4*)(W1 + e);
        split_store(sm, OFF_W1H, OFF_W1L, row, k,     v1.x, v1.y);
        split_store(sm, OFF_W1H, OFF_W1L, row, k + 2, v1.z, v1.w);
        const float4 v2 = *(const float4*)(W2 + e);
        split_store(sm, OFF_W2H, OFF_W2L, row, k,     v2.x, v2.y);
        split_store(sm, OFF_W2H, OFF_W2L, row, k + 2, v2.z, v2.w);
    }
    if (tid < 128)      ((float*)(sm + OFF_B1))[tid] = b1[tid];
    else if (tid < 256) ((float*)(sm + OFF_B2))[tid - 128] = b2[tid - 128];
    __syncthreads();  // only sync in the kernel

    const float* sB1 = (const float*)(sm + OFF_B1);
    const float* sB2 = (const float*)(sm + OFF_B2);

    // lane geometry
    const int r0 = lane >> 2;             // row within 16-row band (and +8)
    const int kp = (lane & 3) * 2;        // col-pair base
    const int g = lane >> 3, i = lane & 7;
    const int wRowLoc = ((g >> 1) << 3) + i;  // B-frag n position
    const int wKoff   = (g & 1) << 3;         // B-frag k half

    for (int chunk = blockIdx.x * WARPS + wid; chunk < n_chunks;
         chunk += gridDim.x * WARPS) {
        const int rowBase = chunk * 16;

        const float tv0 = t[rowBase + r0];
        const float tv1 = t[rowBase + r0 + 8];
        const float p10 = tv0 * (PI_F / 128.0f), p20 = (1.0f - tv0) * (PI_F / 128.0f);
        const float p11 = tv1 * (PI_F / 128.0f), p21 = (1.0f - tv1) * (PI_F / 128.0f);

        float acc[16][4];
#pragma unroll
        for (int nt = 0; nt < 16; ++nt)
#pragma unroll
            for (int q = 0; q < 4; ++q) acc[nt][q] = 0.0f;

        // ---- GEMM1: emb a-frags computed on the fly ----
#pragma unroll
        for (int ks = 0; ks < 8; ++ks) {
            const int kb = ks * 16;
            const float dA = (float)(kb + kp), dB = dA + 1.0f;
            const float dC = dA + 8.0f,       dD = dA + 9.0f;
            uint32_t ah[4], al[4];
            split2(emb_f(tv0, p10, p20, dA), emb_f(tv0, p10, p20, dB), ah[0], al[0]);
            split2(emb_f(tv1, p11, p21, dA), emb_f(tv1, p11, p21, dB), ah[1], al[1]);
            split2(emb_f(tv0, p10, p20, dC), emb_f(tv0, p10, p20, dD), ah[2], al[2]);
            split2(emb_f(tv1, p11, p21, dC), emb_f(tv1, p11, p21, dD), ah[3], al[3]);
#pragma unroll
            for (int nt = 0; nt < 8; ++nt) {
                const uint32_t wa = swz(nt * 16 + wRowLoc, kb + wKoff);
                uint32_t bh[4], bl[4];
                ldsm4(bh[0], bh[1], bh[2], bh[3], sb + OFF_W1H + wa);
                ldsm4(bl[0], bl[1], bl[2], bl[3], sb + OFF_W1L + wa);
                mma16816(acc[2 * nt],     ah, bh[0], bh[1]);
                mma16816(acc[2 * nt],     al, bh[0], bh[1]);
                mma16816(acc[2 * nt],     ah, bl[0], bl[1]);
                mma16816(acc[2 * nt + 1], ah, bh[2], bh[3]);
                mma16816(acc[2 * nt + 1], al, bh[2], bh[3]);
                mma16816(acc[2 * nt + 1], ah, bl[2], bl[3]);
            }
        }

        // ---- epilogue 1 in registers: bias + silu -> layer-2 A-frags ----
        uint32_t ha[8][4], la[8][4];
#pragma unroll
        for (int ks = 0; ks < 8; ++ks) {
            const float2 bA = *(const float2*)(sB1 + ks * 16 + kp);
            const float2 bB = *(const float2*)(sB1 + ks * 16 + 8 + kp);
            const float* c0 = acc[2 * ks];
            const float* c1 = acc[2 * ks + 1];
            split2(silu_f(c0[0] + bA.x), silu_f(c0[1] + bA.y), ha[ks][0], la[ks][0]);
            split2(silu_f(c0[2] + bA.x), silu_f(c0[3] + bA.y), ha[ks][1], la[ks][1]);
            split2(silu_f(c1[0] + bB.x), silu_f(c1[1] + bB.y), ha[ks][2], la[ks][2]);
            split2(silu_f(c1[2] + bB.x), silu_f(c1[3] + bB.y), ha[ks][3], la[ks][3]);
        }

        // ---- GEMM2 ----
#pragma unroll
        for (int nt = 0; nt < 16; ++nt)
#pragma unroll
            for (int q = 0; q < 4; ++q) acc[nt][q] = 0.0f;
#pragma unroll
        for (int ks = 0; ks < 8; ++ks) {
            const int kb = ks * 16;
#pragma unroll
            for (int nt = 0; nt < 8; ++nt) {
                const uint32_t wa = swz(nt * 16 + wRowLoc, kb + wKoff);
                uint32_t bh[4], bl[4];
                ldsm4(bh[0], bh[1], bh[2], bh[3], sb + OFF_W2H + wa);
                ldsm4(bl[0], bl[1], bl[2], bl[3], sb + OFF_W2L + wa);
                mma16816(acc[2 * nt],     ha[ks], bh[0], bh[1]);
                mma16816(acc[2 * nt],     la[ks], bh[0], bh[1]);
                mma16816(acc[2 * nt],     ha[ks], bl[0], bl[1]);
                mma16816(acc[2 * nt + 1], ha[ks], bh[2], bh[3]);
                mma16816(acc[2 * nt + 1], la[ks], bh[2], bh[3]);
                mma16816(acc[2 * nt + 1], ha[ks], bl[2], bl[3]);
            }
        }

        // ---- epilogue 2: bias + silu -> gmem ----
        float* o0 = out + (size_t)(rowBase + r0) * DIM;
        float* o1 = out + (size_t)(rowBase + r0 + 8) * DIM;
#pragma unroll
        for (int nt = 0; nt < 16; ++nt) {
            const int c = nt * 8 + kp;
            const float2 bb = *(const float2*)(sB2 + c);
            const float* a4 = acc[nt];
            *(float2*)(o0 + c) = make_float2(silu_f(a4[0] + bb.x), silu_f(a4[1] + bb.y));
            *(float2*)(o1 + c) = make_float2(silu_f(a4[2] + bb.x), silu_f(a4[3] + bb.y));
        }
    }
}

extern "C" void kernel_launch(void* const* d_in, const int* in_sizes, int n_in,
                              void* d_out, int out_size) {
    const float* t  = (const float*)d_in[0];
    const float* W1 = (const float*)d_in[1];
    const float* b1 = (const float*)d_in[2];
    const float* W2 = (const float*)d_in[3];
    const float* b2 = (const float*)d_in[4];
    float* out = (float*)d_out;

    const int B = in_sizes[0];
    const int n_chunks = B / 16;

    int nsm = 148;
    cudaDeviceGetAttribute(&nsm, cudaDevAttrMultiProcessorCount, 0);

    cudaFuncSetAttribute(fused_timestep_mlp_rr,
                         cudaFuncAttributeMaxDynamicSharedMemorySize, SMEM_TOTAL);

    fused_timestep_mlp_rr<<<nsm, NTH, SMEM_TOTAL>>>(t, W1, b1, W2, b2, out, n_chunks);
}